// round 1
// baseline (speedup 1.0000x reference)
#include <cuda_runtime.h>

// NonLocalAttention: B=8, C=256, Ci=128, H=W=64, N=4096, M=1024
#define BB 8
#define CC 256
#define CI 128
#define HH 64
#define WW 64
#define NN 4096
#define MM 1024

// Scratch (allocation-free: __device__ globals)
__device__ float g_theta[(size_t)BB * NN * CI];   // [B][N][Ci]
__device__ float g_phif [(size_t)BB * NN * CI];   // full-res phi conv
__device__ float g_gf   [(size_t)BB * NN * CI];   // full-res g conv
__device__ float g_phip [(size_t)BB * MM * CI];   // pooled phi [B][M][Ci]
__device__ float g_gp   [(size_t)BB * MM * CI];   // pooled g   [B][M][Ci]
__device__ float g_y    [(size_t)BB * NN * CI];   // attention out [B][N][Ci]

// ---------------------------------------------------------------------------
// Kernel 1: three 1x1 convs in one pass.
// out[b][n][ci] = sum_c x[b][c][n] * w[ci][c] + bias[ci]  for w in {theta,phi,g}
// Tile: 64 n  x 64 ci, 256 threads, 4x4 micro-tile per proj.
// tx -> ci (coalesced [n][ci] writes), ty -> n.
// ---------------------------------------------------------------------------
__global__ __launch_bounds__(256) void proj3_kernel(
    const float* __restrict__ x,
    const float* __restrict__ w_t, const float* __restrict__ b_t,
    const float* __restrict__ w_p, const float* __restrict__ b_p,
    const float* __restrict__ w_g, const float* __restrict__ b_g)
{
    __shared__ float xs[16][64];        // [cc][n_local]
    __shared__ float ws[3][16][68];     // [proj][cc][ci_local], padded

    const int b   = blockIdx.z;
    const int ci0 = blockIdx.y * 64;
    const int n0  = blockIdx.x * 64;
    const int tid = threadIdx.x;
    const int tx  = tid & 15;           // ci quad
    const int ty  = tid >> 4;           // n quad

    float at[4][4] = {}, ap[4][4] = {}, ag[4][4] = {};

    const float* xb = x + (size_t)b * CC * NN;
    const float* wlist[3] = {w_t, w_p, w_g};

    for (int c0 = 0; c0 < CC; c0 += 16) {
        __syncthreads();
        // load x tile (coalesced along n)
        #pragma unroll
        for (int k2 = 0; k2 < 4; k2++) {
            int idx = tid + k2 * 256;
            int cc = idx >> 6, nl = idx & 63;
            xs[cc][nl] = xb[(size_t)(c0 + cc) * NN + n0 + nl];
        }
        // load weight tiles transposed
        #pragma unroll
        for (int p = 0; p < 3; p++) {
            const float* w = wlist[p];
            #pragma unroll
            for (int k2 = 0; k2 < 4; k2++) {
                int idx = tid + k2 * 256;
                int cil = idx >> 4, cc = idx & 15;
                ws[p][cc][cil] = w[(size_t)(ci0 + cil) * CC + c0 + cc];
            }
        }
        __syncthreads();

        #pragma unroll
        for (int cc = 0; cc < 16; cc++) {
            float4 xv  = *(const float4*)&xs[cc][ty * 4];
            float4 wv0 = *(const float4*)&ws[0][cc][tx * 4];
            float4 wv1 = *(const float4*)&ws[1][cc][tx * 4];
            float4 wv2 = *(const float4*)&ws[2][cc][tx * 4];
            float xa[4]  = {xv.x, xv.y, xv.z, xv.w};
            float w0a[4] = {wv0.x, wv0.y, wv0.z, wv0.w};
            float w1a[4] = {wv1.x, wv1.y, wv1.z, wv1.w};
            float w2a[4] = {wv2.x, wv2.y, wv2.z, wv2.w};
            #pragma unroll
            for (int i = 0; i < 4; i++) {
                #pragma unroll
                for (int j = 0; j < 4; j++) {
                    at[i][j] = fmaf(xa[i], w0a[j], at[i][j]);
                    ap[i][j] = fmaf(xa[i], w1a[j], ap[i][j]);
                    ag[i][j] = fmaf(xa[i], w2a[j], ag[i][j]);
                }
            }
        }
    }

    const int ci = ci0 + tx * 4;
    float4 bt4 = *(const float4*)&b_t[ci];
    float4 bp4 = *(const float4*)&b_p[ci];
    float4 bg4 = *(const float4*)&b_g[ci];
    float bta[4] = {bt4.x, bt4.y, bt4.z, bt4.w};
    float bpa[4] = {bp4.x, bp4.y, bp4.z, bp4.w};
    float bga[4] = {bg4.x, bg4.y, bg4.z, bg4.w};

    #pragma unroll
    for (int i = 0; i < 4; i++) {
        size_t off = ((size_t)b * NN + n0 + ty * 4 + i) * CI + ci;
        float4 vt = {at[i][0] + bta[0], at[i][1] + bta[1], at[i][2] + bta[2], at[i][3] + bta[3]};
        float4 vp = {ap[i][0] + bpa[0], ap[i][1] + bpa[1], ap[i][2] + bpa[2], ap[i][3] + bpa[3]};
        float4 vg = {ag[i][0] + bga[0], ag[i][1] + bga[1], ag[i][2] + bga[2], ag[i][3] + bga[3]};
        *(float4*)&g_theta[off] = vt;
        *(float4*)&g_phif[off]  = vp;
        *(float4*)&g_gf[off]    = vg;
    }
}

// ---------------------------------------------------------------------------
// Kernel 2: 2x2 maxpool of phi_full/g_full  [B][N][Ci] -> [B][M][Ci]
// ---------------------------------------------------------------------------
__global__ __launch_bounds__(256) void pool_kernel()
{
    int idx = blockIdx.x * 256 + threadIdx.x;     // BB*MM*(CI/4) = 262144
    int c4 = (idx & 31) * 4;
    int m  = (idx >> 5) & (MM - 1);
    int b  = idx >> 15;
    int hp = m >> 5, wp = m & 31;
    int n00 = (hp * 2) * WW + wp * 2;
    size_t base = ((size_t)b * NN + n00) * CI + c4;
    size_t dst  = ((size_t)b * MM + m) * CI + c4;

    float4 a0 = *(const float4*)&g_phif[base];
    float4 a1 = *(const float4*)&g_phif[base + CI];
    float4 a2 = *(const float4*)&g_phif[base + (size_t)WW * CI];
    float4 a3 = *(const float4*)&g_phif[base + (size_t)WW * CI + CI];
    float4 r;
    r.x = fmaxf(fmaxf(a0.x, a1.x), fmaxf(a2.x, a3.x));
    r.y = fmaxf(fmaxf(a0.y, a1.y), fmaxf(a2.y, a3.y));
    r.z = fmaxf(fmaxf(a0.z, a1.z), fmaxf(a2.z, a3.z));
    r.w = fmaxf(fmaxf(a0.w, a1.w), fmaxf(a2.w, a3.w));
    *(float4*)&g_phip[dst] = r;

    a0 = *(const float4*)&g_gf[base];
    a1 = *(const float4*)&g_gf[base + CI];
    a2 = *(const float4*)&g_gf[base + (size_t)WW * CI];
    a3 = *(const float4*)&g_gf[base + (size_t)WW * CI + CI];
    r.x = fmaxf(fmaxf(a0.x, a1.x), fmaxf(a2.x, a3.x));
    r.y = fmaxf(fmaxf(a0.y, a1.y), fmaxf(a2.y, a3.y));
    r.z = fmaxf(fmaxf(a0.z, a1.z), fmaxf(a2.z, a3.z));
    r.w = fmaxf(fmaxf(a0.w, a1.w), fmaxf(a2.w, a3.w));
    *(float4*)&g_gp[dst] = r;
}

// ---------------------------------------------------------------------------
// Kernel 3: flash-style attention.
// Per block: 64 queries, loop over M=1024 keys in tiles of 64, online softmax.
// smem: Qt/Kt stored k-major (transposed, pad 68) so S-loop is pure float4.
// ---------------------------------------------------------------------------
#define ATTN_SMEM_FLOATS (128*68 + 128*68 + 64*128 + 64*64)
__global__ __launch_bounds__(256) void attn_kernel()
{
    extern __shared__ float sm[];
    float* Qt = sm;                    // [k=128][q=64] pad 68
    float* Kt = Qt + 128 * 68;         // [k=128][m=64] pad 68
    float* Vs = Kt + 128 * 68;         // [m=64][ci=128]
    float* Ps = Vs + 64 * 128;         // [q=64][m=64]

    const int b  = blockIdx.y;
    const int n0 = blockIdx.x * 64;
    const int tid = threadIdx.x;
    const int tx = tid & 15;
    const int ty = tid >> 4;

    // load Q transposed
    const float* Qg = g_theta + ((size_t)b * NN + n0) * CI;
    #pragma unroll 8
    for (int k2 = 0; k2 < 32; k2++) {
        int idx = tid + k2 * 256;
        int r = idx >> 7, k = idx & 127;
        Qt[k * 68 + r] = Qg[(size_t)r * CI + k];
    }

    float m_i[4], l_i[4], o[4][8];
    #pragma unroll
    for (int i = 0; i < 4; i++) {
        m_i[i] = -1e30f; l_i[i] = 0.f;
        #pragma unroll
        for (int c = 0; c < 8; c++) o[i][c] = 0.f;
    }

    for (int m0 = 0; m0 < MM; m0 += 64) {
        __syncthreads();   // covers initial Qt publish + protects Kt/Vs reuse
        const float* Kg = g_phip + ((size_t)b * MM + m0) * CI;
        const float* Vg = g_gp   + ((size_t)b * MM + m0) * CI;
        #pragma unroll 8
        for (int k2 = 0; k2 < 32; k2++) {
            int idx = tid + k2 * 256;
            int r = idx >> 7, k = idx & 127;
            Kt[k * 68 + r] = Kg[(size_t)r * CI + k];
            Vs[idx]        = Vg[idx];
        }
        __syncthreads();

        // S = Q K^T  (4x4 per thread)
        float s[4][4] = {};
        #pragma unroll 8
        for (int k = 0; k < 128; k++) {
            float4 qv = *(const float4*)&Qt[k * 68 + ty * 4];
            float4 kv = *(const float4*)&Kt[k * 68 + tx * 4];
            float qa[4] = {qv.x, qv.y, qv.z, qv.w};
            float ka[4] = {kv.x, kv.y, kv.z, kv.w};
            #pragma unroll
            for (int i = 0; i < 4; i++)
                #pragma unroll
                for (int j = 0; j < 4; j++)
                    s[i][j] = fmaf(qa[i], ka[j], s[i][j]);
        }

        // online softmax per query row (row owned by a 16-lane group)
        #pragma unroll
        for (int i = 0; i < 4; i++) {
            float mx = fmaxf(fmaxf(s[i][0], s[i][1]), fmaxf(s[i][2], s[i][3]));
            #pragma unroll
            for (int off = 8; off >= 1; off >>= 1)
                mx = fmaxf(mx, __shfl_xor_sync(0xffffffffu, mx, off));
            float mnew  = fmaxf(m_i[i], mx);
            float alpha = __expf(m_i[i] - mnew);
            float p0 = __expf(s[i][0] - mnew);
            float p1 = __expf(s[i][1] - mnew);
            float p2 = __expf(s[i][2] - mnew);
            float p3 = __expf(s[i][3] - mnew);
            float ls = p0 + p1 + p2 + p3;
            #pragma unroll
            for (int off = 8; off >= 1; off >>= 1)
                ls += __shfl_xor_sync(0xffffffffu, ls, off);
            l_i[i] = l_i[i] * alpha + ls;
            m_i[i] = mnew;
            #pragma unroll
            for (int c = 0; c < 8; c++) o[i][c] *= alpha;
            float4 pv4 = {p0, p1, p2, p3};
            *(float4*)&Ps[(ty * 4 + i) * 64 + tx * 4] = pv4;
        }
        __syncthreads();

        // O += P V
        #pragma unroll 4
        for (int m = 0; m < 64; m++) {
            float4 v0 = *(const float4*)&Vs[m * 128 + tx * 8];
            float4 v1 = *(const float4*)&Vs[m * 128 + tx * 8 + 4];
            #pragma unroll
            for (int i = 0; i < 4; i++) {
                float pp = Ps[(ty * 4 + i) * 64 + m];
                o[i][0] = fmaf(pp, v0.x, o[i][0]);
                o[i][1] = fmaf(pp, v0.y, o[i][1]);
                o[i][2] = fmaf(pp, v0.z, o[i][2]);
                o[i][3] = fmaf(pp, v0.w, o[i][3]);
                o[i][4] = fmaf(pp, v1.x, o[i][4]);
                o[i][5] = fmaf(pp, v1.y, o[i][5]);
                o[i][6] = fmaf(pp, v1.z, o[i][6]);
                o[i][7] = fmaf(pp, v1.w, o[i][7]);
            }
        }
    }

    // normalize + store y[b][n][ci]
    float* yb = g_y + ((size_t)b * NN + n0) * CI;
    #pragma unroll
    for (int i = 0; i < 4; i++) {
        float inv = 1.f / l_i[i];
        int r = ty * 4 + i;
        float4 w0 = {o[i][0] * inv, o[i][1] * inv, o[i][2] * inv, o[i][3] * inv};
        float4 w1 = {o[i][4] * inv, o[i][5] * inv, o[i][6] * inv, o[i][7] * inv};
        *(float4*)&yb[(size_t)r * CI + tx * 8]     = w0;
        *(float4*)&yb[(size_t)r * CI + tx * 8 + 4] = w1;
    }
}

// ---------------------------------------------------------------------------
// Kernel 4: output conv + bias + residual.
// out[b][c][n] = x[b][c][n] + b_out[c] + sum_ci w_out[c][ci] * y[b][n][ci]
// Tile 64c x 64n, 256 threads; tx -> n (coalesced writes), ty -> c.
// ---------------------------------------------------------------------------
__global__ __launch_bounds__(256) void out_kernel(
    const float* __restrict__ x,
    const float* __restrict__ wo, const float* __restrict__ bo,
    float* __restrict__ out)
{
    __shared__ float wtile[16][68];   // [cc][c_local]
    __shared__ float ytile[16][68];   // [cc][n_local]

    const int b  = blockIdx.z;
    const int c0 = blockIdx.y * 64;
    const int n0 = blockIdx.x * 64;
    const int tid = threadIdx.x;
    const int tx = tid & 15;
    const int ty = tid >> 4;

    float acc[4][4] = {};
    const float* yb = g_y + ((size_t)b * NN + n0) * CI;

    for (int k0 = 0; k0 < CI; k0 += 16) {
        __syncthreads();
        #pragma unroll
        for (int k2 = 0; k2 < 4; k2++) {
            int idx = tid + k2 * 256;
            int rl = idx >> 4, cc = idx & 15;
            wtile[cc][rl] = wo[(size_t)(c0 + rl) * CI + k0 + cc];
            ytile[cc][rl] = yb[(size_t)rl * CI + k0 + cc];
        }
        __syncthreads();
        #pragma unroll
        for (int cc = 0; cc < 16; cc++) {
            float4 wv = *(const float4*)&wtile[cc][ty * 4];
            float4 yv = *(const float4*)&ytile[cc][tx * 4];
            float wa[4] = {wv.x, wv.y, wv.z, wv.w};
            float ya[4] = {yv.x, yv.y, yv.z, yv.w};
            #pragma unroll
            for (int i = 0; i < 4; i++)
                #pragma unroll
                for (int j = 0; j < 4; j++)
                    acc[i][j] = fmaf(wa[i], ya[j], acc[i][j]);
        }
    }

    #pragma unroll
    for (int i = 0; i < 4; i++) {
        int c = c0 + ty * 4 + i;
        float bias = __ldg(&bo[c]);
        size_t off = ((size_t)b * CC + c) * NN + n0 + tx * 4;
        float4 xv = *(const float4*)&x[off];
        float4 r  = {acc[i][0] + xv.x + bias, acc[i][1] + xv.y + bias,
                     acc[i][2] + xv.z + bias, acc[i][3] + xv.w + bias};
        *(float4*)&out[off] = r;
    }
}

// ---------------------------------------------------------------------------
extern "C" void kernel_launch(void* const* d_in, const int* in_sizes, int n_in,
                              void* d_out, int out_size)
{
    const float* x  = (const float*)d_in[0];
    const float* wt = (const float*)d_in[1];
    const float* bt = (const float*)d_in[2];
    const float* wp = (const float*)d_in[3];
    const float* bp = (const float*)d_in[4];
    const float* wg = (const float*)d_in[5];
    const float* bg = (const float*)d_in[6];
    const float* wo = (const float*)d_in[7];
    const float* bo = (const float*)d_in[8];
    float* out = (float*)d_out;

    const int attn_smem = ATTN_SMEM_FLOATS * (int)sizeof(float);   // 118784 B
    cudaFuncSetAttribute(attn_kernel, cudaFuncAttributeMaxDynamicSharedMemorySize, attn_smem);

    proj3_kernel<<<dim3(NN / 64, CI / 64, BB), 256>>>(x, wt, bt, wp, bp, wg, bg);
    pool_kernel<<<(BB * MM * (CI / 4)) / 256, 256>>>();
    attn_kernel<<<dim3(NN / 64, BB), 256, attn_smem>>>();
    out_kernel<<<dim3(NN / 64, CC / 64, BB), 256>>>(x, wo, bo, out);
}

// round 2
// speedup vs baseline: 2.1822x; 2.1822x over previous
#include <cuda_runtime.h>

// NonLocalAttention: B=8, C=256, Ci=128, H=W=64, N=4096, M=1024
#define BB 8
#define CC 256
#define CI 128
#define WW 64
#define NN 4096
#define MM 1024

// Scratch (allocation-free: __device__ globals)
__device__ float g_theta[(size_t)BB * NN * CI];
__device__ float g_phif [(size_t)BB * NN * CI];
__device__ float g_gf   [(size_t)BB * NN * CI];
__device__ float g_phip [(size_t)BB * MM * CI];
__device__ float g_gp   [(size_t)BB * MM * CI];
__device__ float g_y    [(size_t)BB * NN * CI];

// ---------------------------------------------------------------------------
// tf32 mma helpers
// ---------------------------------------------------------------------------
__device__ __forceinline__ unsigned cvt_tf32(float x) {
    unsigned u;
    asm("cvt.rna.tf32.f32 %0, %1;" : "=r"(u) : "f"(x));
    return u;
}
__device__ __forceinline__ void splitf(float x, float& h, float& l) {
    unsigned hu = cvt_tf32(x);
    h = __uint_as_float(hu);
    l = __uint_as_float(cvt_tf32(x - h));
}
__device__ __forceinline__ void split4(float4 v, float4& h, float4& l) {
    splitf(v.x, h.x, l.x); splitf(v.y, h.y, l.y);
    splitf(v.z, h.z, l.z); splitf(v.w, h.w, l.w);
}
__device__ __forceinline__ void mma8(float* c, unsigned a0, unsigned a1,
                                     unsigned a2, unsigned a3,
                                     unsigned b0, unsigned b1) {
    asm volatile(
        "mma.sync.aligned.m16n8k8.row.col.f32.tf32.tf32.f32 "
        "{%0,%1,%2,%3},{%4,%5,%6,%7},{%8,%9},{%0,%1,%2,%3};\n"
        : "+f"(c[0]), "+f"(c[1]), "+f"(c[2]), "+f"(c[3])
        : "r"(a0), "r"(a1), "r"(a2), "r"(a3), "r"(b0), "r"(b1));
}
#define FB(p) __float_as_uint(p)

// ---------------------------------------------------------------------------
// Kernel 1: 3-way 1x1 conv. C[n][j] = sum_c x[c][n] * w[j][c] + bias[j]
// grid (N/64, 6, B). blockIdx.y: 0,1=theta 2,3=phi 4,5=g ; 64-wide j tile.
// Block 64n x 64j, 8 warps (4M x 2N), warp 16n x 32j. K chunks of 32. 3xTF32.
// ---------------------------------------------------------------------------
__global__ __launch_bounds__(256) void proj3_tc(
    const float* __restrict__ x,
    const float* __restrict__ w_t, const float* __restrict__ b_t,
    const float* __restrict__ w_p, const float* __restrict__ b_p,
    const float* __restrict__ w_g, const float* __restrict__ b_g)
{
    __shared__ float Ah[32 * 72], Al[32 * 72];   // [k][n] pitch 72 (=8 mod 32)
    __shared__ float Bh[64 * 36], Bl[64 * 36];   // [j][k] pitch 36 (=4 mod 32)

    const int b  = blockIdx.z;
    const int n0 = blockIdx.x * 64;
    const int yy = blockIdx.y;

    const float* w;  const float* bias;  float* dst;
    if (yy < 2)      { w = w_t; bias = b_t; dst = g_theta; }
    else if (yy < 4) { w = w_p; bias = b_p; dst = g_phif; }
    else             { w = w_g; bias = b_g; dst = g_gf;  }
    const int cib = (yy & 1) * 64;

    const int tid  = threadIdx.x;
    const int lane = tid & 31, warp = tid >> 5;
    const int gid  = lane >> 2, t4 = lane & 3;
    const int mw   = (warp >> 1) * 16, nw = (warp & 1) * 32;

    float acc[4][4] = {};
    const float* xb = x + (size_t)b * CC * NN;

    for (int c0 = 0; c0 < CC; c0 += 32) {
        __syncthreads();
        #pragma unroll
        for (int it = 0; it < 2; it++) {
            int j = tid + it * 256;
            int kk = j >> 4, n4 = (j & 15) * 4;
            float4 v = *(const float4*)&xb[(size_t)(c0 + kk) * NN + n0 + n4];
            float4 h, l; split4(v, h, l);
            *(float4*)&Ah[kk * 72 + n4] = h;
            *(float4*)&Al[kk * 72 + n4] = l;
            int jj = j >> 3, k4 = (j & 7) * 4;
            float4 wv = *(const float4*)&w[(size_t)(cib + jj) * CC + c0 + k4];
            split4(wv, h, l);
            *(float4*)&Bh[jj * 36 + k4] = h;
            *(float4*)&Bl[jj * 36 + k4] = l;
        }
        __syncthreads();

        #pragma unroll
        for (int ks = 0; ks < 4; ks++) {
            int ko = ks * 8 + t4;
            unsigned ah[4] = {FB(Ah[ko * 72 + mw + gid]),     FB(Ah[ko * 72 + mw + gid + 8]),
                              FB(Ah[(ko + 4) * 72 + mw + gid]), FB(Ah[(ko + 4) * 72 + mw + gid + 8])};
            unsigned al[4] = {FB(Al[ko * 72 + mw + gid]),     FB(Al[ko * 72 + mw + gid + 8]),
                              FB(Al[(ko + 4) * 72 + mw + gid]), FB(Al[(ko + 4) * 72 + mw + gid + 8])};
            #pragma unroll
            for (int nt = 0; nt < 4; nt++) {
                int jj = nw + nt * 8 + gid;
                unsigned bh0 = FB(Bh[jj * 36 + ko]), bh1 = FB(Bh[jj * 36 + ko + 4]);
                unsigned bl0 = FB(Bl[jj * 36 + ko]), bl1 = FB(Bl[jj * 36 + ko + 4]);
                mma8(acc[nt], ah[0], ah[1], ah[2], ah[3], bh0, bh1);
                mma8(acc[nt], ah[0], ah[1], ah[2], ah[3], bl0, bl1);
                mma8(acc[nt], al[0], al[1], al[2], al[3], bh0, bh1);
            }
        }
    }

    const size_t base = (size_t)b * NN + n0;
    #pragma unroll
    for (int nt = 0; nt < 4; nt++) {
        int col = cib + nw + nt * 8 + 2 * t4;
        float bb0 = bias[col], bb1 = bias[col + 1];
        int r0 = mw + gid;
        float2 v0 = {acc[nt][0] + bb0, acc[nt][1] + bb1};
        float2 v1 = {acc[nt][2] + bb0, acc[nt][3] + bb1};
        *(float2*)&dst[(base + r0) * CI + col]     = v0;
        *(float2*)&dst[(base + r0 + 8) * CI + col] = v1;
    }
}

// ---------------------------------------------------------------------------
// Kernel 2: 2x2 maxpool [B][N][Ci] -> [B][M][Ci]
// ---------------------------------------------------------------------------
__global__ __launch_bounds__(256) void pool_kernel()
{
    int idx = blockIdx.x * 256 + threadIdx.x;
    int c4 = (idx & 31) * 4;
    int m  = (idx >> 5) & (MM - 1);
    int b  = idx >> 15;
    int hp = m >> 5, wp = m & 31;
    int n00 = (hp * 2) * WW + wp * 2;
    size_t base = ((size_t)b * NN + n00) * CI + c4;
    size_t dst  = ((size_t)b * MM + m) * CI + c4;

    float4 a0 = *(const float4*)&g_phif[base];
    float4 a1 = *(const float4*)&g_phif[base + CI];
    float4 a2 = *(const float4*)&g_phif[base + (size_t)WW * CI];
    float4 a3 = *(const float4*)&g_phif[base + (size_t)WW * CI + CI];
    float4 r;
    r.x = fmaxf(fmaxf(a0.x, a1.x), fmaxf(a2.x, a3.x));
    r.y = fmaxf(fmaxf(a0.y, a1.y), fmaxf(a2.y, a3.y));
    r.z = fmaxf(fmaxf(a0.z, a1.z), fmaxf(a2.z, a3.z));
    r.w = fmaxf(fmaxf(a0.w, a1.w), fmaxf(a2.w, a3.w));
    *(float4*)&g_phip[dst] = r;

    a0 = *(const float4*)&g_gf[base];
    a1 = *(const float4*)&g_gf[base + CI];
    a2 = *(const float4*)&g_gf[base + (size_t)WW * CI];
    a3 = *(const float4*)&g_gf[base + (size_t)WW * CI + CI];
    r.x = fmaxf(fmaxf(a0.x, a1.x), fmaxf(a2.x, a3.x));
    r.y = fmaxf(fmaxf(a0.y, a1.y), fmaxf(a2.y, a3.y));
    r.z = fmaxf(fmaxf(a0.z, a1.z), fmaxf(a2.z, a3.z));
    r.w = fmaxf(fmaxf(a0.w, a1.w), fmaxf(a2.w, a3.w));
    *(float4*)&g_gp[dst] = r;
}

// ---------------------------------------------------------------------------
// Kernel 3: flash attention, tf32 mma.
// Block: 128 q, 8 warps (16 q each, full 64-m stripe). 16 chunks of 64 m.
// S = QK^T with 3xTF32 split; PV with P_hi x V_hi (error ~3e-4, fine).
// ---------------------------------------------------------------------------
#define QP 132
#define KP 132
#define VP 136
#define PP 68
#define ATTN_SMEM_BYTES ((128*QP + 2*64*KP + 64*VP + 128*PP) * 4)

__global__ __launch_bounds__(256, 1) void attn_tc()
{
    extern __shared__ float sm[];
    float* Qs = sm;                    // [q=128][k=128] pitch 132
    float* Kh = Qs + 128 * QP;         // [m=64][k=128] pitch 132 (tf32 hi)
    float* Kl = Kh + 64 * KP;          // (tf32 lo)
    float* Vh = Kl + 64 * KP;          // [m=64][ci=128] pitch 136 (tf32 hi)
    float* Ps = Vh + 64 * VP;          // [q=128][m=64] pitch 68

    const int b  = blockIdx.y;
    const int n0 = blockIdx.x * 128;
    const int tid  = threadIdx.x;
    const int lane = tid & 31, warp = tid >> 5;
    const int gid  = lane >> 2, t4 = lane & 3;
    const int qw   = warp * 16;

    // stage Q once (fp32; hi/lo split per use — reused 16x so cvt cost is small)
    const float* Qg = g_theta + ((size_t)b * NN + n0) * CI;
    #pragma unroll
    for (int it = 0; it < 16; it++) {
        int j = tid + it * 256;
        int q = j >> 5, k4 = (j & 31) * 4;
        *(float4*)&Qs[q * QP + k4] = *(const float4*)&Qg[(size_t)q * CI + k4];
    }

    float o[16][4];
    #pragma unroll
    for (int i = 0; i < 16; i++)
        #pragma unroll
        for (int jj = 0; jj < 4; jj++) o[i][jj] = 0.f;
    float m_lo = -1e30f, m_hi = -1e30f, l_lo = 0.f, l_hi = 0.f;

    for (int m0 = 0; m0 < MM; m0 += 64) {
        __syncthreads();
        const float* Kg = g_phip + ((size_t)b * MM + m0) * CI;
        const float* Vg = g_gp   + ((size_t)b * MM + m0) * CI;
        #pragma unroll
        for (int it = 0; it < 8; it++) {
            int j = tid + it * 256;
            int m = j >> 5, k4 = (j & 31) * 4;
            float4 v = *(const float4*)&Kg[(size_t)m * CI + k4];
            float4 h, l; split4(v, h, l);
            *(float4*)&Kh[m * KP + k4] = h;
            *(float4*)&Kl[m * KP + k4] = l;
            float4 vv = *(const float4*)&Vg[(size_t)m * CI + k4];
            float4 vh, vl; split4(vv, vh, vl);
            *(float4*)&Vh[m * VP + k4] = vh;
        }
        __syncthreads();

        // S = Q K^T : per warp 16q x 64m
        float s[8][4];
        #pragma unroll
        for (int nt = 0; nt < 8; nt++)
            #pragma unroll
            for (int jj = 0; jj < 4; jj++) s[nt][jj] = 0.f;

        #pragma unroll
        for (int ks = 0; ks < 16; ks++) {
            int ko = ks * 8 + t4;
            float aq0 = Qs[(qw + gid) * QP + ko];
            float aq1 = Qs[(qw + gid + 8) * QP + ko];
            float aq2 = Qs[(qw + gid) * QP + ko + 4];
            float aq3 = Qs[(qw + gid + 8) * QP + ko + 4];
            float h, l;
            unsigned ah[4], al[4];
            splitf(aq0, h, l); ah[0] = FB(h); al[0] = FB(l);
            splitf(aq1, h, l); ah[1] = FB(h); al[1] = FB(l);
            splitf(aq2, h, l); ah[2] = FB(h); al[2] = FB(l);
            splitf(aq3, h, l); ah[3] = FB(h); al[3] = FB(l);
            #pragma unroll
            for (int nt = 0; nt < 8; nt++) {
                int mr = nt * 8 + gid;
                unsigned bh0 = FB(Kh[mr * KP + ko]), bh1 = FB(Kh[mr * KP + ko + 4]);
                unsigned bl0 = FB(Kl[mr * KP + ko]), bl1 = FB(Kl[mr * KP + ko + 4]);
                mma8(s[nt], ah[0], ah[1], ah[2], ah[3], bh0, bh1);
                mma8(s[nt], ah[0], ah[1], ah[2], ah[3], bl0, bl1);
                mma8(s[nt], al[0], al[1], al[2], al[3], bh0, bh1);
            }
        }

        // online softmax (rows qw+gid and qw+gid+8; row spread over quad lanes)
        float mx0 = -1e30f, mx1 = -1e30f;
        #pragma unroll
        for (int nt = 0; nt < 8; nt++) {
            mx0 = fmaxf(mx0, fmaxf(s[nt][0], s[nt][1]));
            mx1 = fmaxf(mx1, fmaxf(s[nt][2], s[nt][3]));
        }
        mx0 = fmaxf(mx0, __shfl_xor_sync(0xffffffffu, mx0, 1));
        mx0 = fmaxf(mx0, __shfl_xor_sync(0xffffffffu, mx0, 2));
        mx1 = fmaxf(mx1, __shfl_xor_sync(0xffffffffu, mx1, 1));
        mx1 = fmaxf(mx1, __shfl_xor_sync(0xffffffffu, mx1, 2));
        float mn0 = fmaxf(m_lo, mx0), mn1 = fmaxf(m_hi, mx1);
        float al0 = __expf(m_lo - mn0), al1 = __expf(m_hi - mn1);
        float s0 = 0.f, s1 = 0.f;
        #pragma unroll
        for (int nt = 0; nt < 8; nt++) {
            float p0 = __expf(s[nt][0] - mn0);
            float p1 = __expf(s[nt][1] - mn0);
            float p2 = __expf(s[nt][2] - mn1);
            float p3 = __expf(s[nt][3] - mn1);
            s0 += p0 + p1; s1 += p2 + p3;
            float2 w0 = {p0, p1}, w1 = {p2, p3};
            *(float2*)&Ps[(qw + gid) * PP + nt * 8 + 2 * t4]     = w0;
            *(float2*)&Ps[(qw + gid + 8) * PP + nt * 8 + 2 * t4] = w1;
        }
        s0 += __shfl_xor_sync(0xffffffffu, s0, 1);
        s0 += __shfl_xor_sync(0xffffffffu, s0, 2);
        s1 += __shfl_xor_sync(0xffffffffu, s1, 1);
        s1 += __shfl_xor_sync(0xffffffffu, s1, 2);
        l_lo = l_lo * al0 + s0; m_lo = mn0;
        l_hi = l_hi * al1 + s1; m_hi = mn1;
        #pragma unroll
        for (int nt = 0; nt < 16; nt++) {
            o[nt][0] *= al0; o[nt][1] *= al0;
            o[nt][2] *= al1; o[nt][3] *= al1;
        }
        __syncwarp();

        // O += P V  (P_hi x V_hi)
        #pragma unroll
        for (int ks = 0; ks < 8; ks++) {
            int ko = ks * 8 + t4;
            unsigned ph0 = cvt_tf32(Ps[(qw + gid) * PP + ko]);
            unsigned ph1 = cvt_tf32(Ps[(qw + gid + 8) * PP + ko]);
            unsigned ph2 = cvt_tf32(Ps[(qw + gid) * PP + ko + 4]);
            unsigned ph3 = cvt_tf32(Ps[(qw + gid + 8) * PP + ko + 4]);
            #pragma unroll
            for (int nt = 0; nt < 16; nt++) {
                int cc = nt * 8 + gid;
                unsigned b0 = FB(Vh[ko * VP + cc]);
                unsigned b1 = FB(Vh[(ko + 4) * VP + cc]);
                mma8(o[nt], ph0, ph1, ph2, ph3, b0, b1);
            }
        }
    }

    float i0 = 1.f / l_lo, i1 = 1.f / l_hi;
    float* yb = g_y + ((size_t)b * NN + n0) * CI;
    #pragma unroll
    for (int nt = 0; nt < 16; nt++) {
        int cc = nt * 8 + 2 * t4;
        float2 w0 = {o[nt][0] * i0, o[nt][1] * i0};
        float2 w1 = {o[nt][2] * i1, o[nt][3] * i1};
        *(float2*)&yb[(size_t)(qw + gid) * CI + cc]     = w0;
        *(float2*)&yb[(size_t)(qw + gid + 8) * CI + cc] = w1;
    }
}

// ---------------------------------------------------------------------------
// Kernel 4: out conv + bias + residual. out[c][n] = x + bo[c] + sum_ci w[c][ci] y[n][ci]
// Block 64c x 64n, warp 16c x 32n, K=128 in 4 chunks. 3xTF32.
// ---------------------------------------------------------------------------
__global__ __launch_bounds__(256) void out_tc(
    const float* __restrict__ x,
    const float* __restrict__ wo, const float* __restrict__ bo,
    float* __restrict__ out)
{
    __shared__ float Ah[64 * 36], Al[64 * 36];   // w_out [c][k] pitch 36
    __shared__ float Bh[64 * 36], Bl[64 * 36];   // y     [n][k] pitch 36

    const int b  = blockIdx.z;
    const int c0 = blockIdx.y * 64;
    const int n0 = blockIdx.x * 64;
    const int tid  = threadIdx.x;
    const int lane = tid & 31, warp = tid >> 5;
    const int gid  = lane >> 2, t4 = lane & 3;
    const int mw   = (warp >> 1) * 16, nw = (warp & 1) * 32;

    const float* yb = g_y + ((size_t)b * NN + n0) * CI;
    float acc[4][4] = {};

    for (int k0 = 0; k0 < CI; k0 += 32) {
        __syncthreads();
        #pragma unroll
        for (int it = 0; it < 2; it++) {
            int j = tid + it * 256;
            int r = j >> 3, k4 = (j & 7) * 4;
            float4 a = *(const float4*)&wo[(size_t)(c0 + r) * CI + k0 + k4];
            float4 h, l; split4(a, h, l);
            *(float4*)&Ah[r * 36 + k4] = h;
            *(float4*)&Al[r * 36 + k4] = l;
            float4 yv = *(const float4*)&yb[(size_t)r * CI + k0 + k4];
            split4(yv, h, l);
            *(float4*)&Bh[r * 36 + k4] = h;
            *(float4*)&Bl[r * 36 + k4] = l;
        }
        __syncthreads();

        #pragma unroll
        for (int ks = 0; ks < 4; ks++) {
            int ko = ks * 8 + t4;
            unsigned ah[4] = {FB(Ah[(mw + gid) * 36 + ko]),     FB(Ah[(mw + gid + 8) * 36 + ko]),
                              FB(Ah[(mw + gid) * 36 + ko + 4]), FB(Ah[(mw + gid + 8) * 36 + ko + 4])};
            unsigned al[4] = {FB(Al[(mw + gid) * 36 + ko]),     FB(Al[(mw + gid + 8) * 36 + ko]),
                              FB(Al[(mw + gid) * 36 + ko + 4]), FB(Al[(mw + gid + 8) * 36 + ko + 4])};
            #pragma unroll
            for (int nt = 0; nt < 4; nt++) {
                int nn = nw + nt * 8 + gid;
                unsigned bh0 = FB(Bh[nn * 36 + ko]), bh1 = FB(Bh[nn * 36 + ko + 4]);
                unsigned bl0 = FB(Bl[nn * 36 + ko]), bl1 = FB(Bl[nn * 36 + ko + 4]);
                mma8(acc[nt], ah[0], ah[1], ah[2], ah[3], bh0, bh1);
                mma8(acc[nt], ah[0], ah[1], ah[2], ah[3], bl0, bl1);
                mma8(acc[nt], al[0], al[1], al[2], al[3], bh0, bh1);
            }
        }
    }

    #pragma unroll
    for (int nt = 0; nt < 4; nt++) {
        int c = c0 + mw + gid;
        int n = n0 + nw + nt * 8 + 2 * t4;
        float bias0 = bo[c], bias1 = bo[c + 8];
        size_t off0 = ((size_t)b * CC + c) * NN + n;
        size_t off1 = ((size_t)b * CC + c + 8) * NN + n;
        float2 x0 = *(const float2*)&x[off0];
        float2 x1 = *(const float2*)&x[off1];
        float2 r0 = {acc[nt][0] + x0.x + bias0, acc[nt][1] + x0.y + bias0};
        float2 r1 = {acc[nt][2] + x1.x + bias1, acc[nt][3] + x1.y + bias1};
        *(float2*)&out[off0] = r0;
        *(float2*)&out[off1] = r1;
    }
}

// ---------------------------------------------------------------------------
extern "C" void kernel_launch(void* const* d_in, const int* in_sizes, int n_in,
                              void* d_out, int out_size)
{
    const float* x  = (const float*)d_in[0];
    const float* wt = (const float*)d_in[1];
    const float* bt = (const float*)d_in[2];
    const float* wp = (const float*)d_in[3];
    const float* bp = (const float*)d_in[4];
    const float* wg = (const float*)d_in[5];
    const float* bg = (const float*)d_in[6];
    const float* wo = (const float*)d_in[7];
    const float* bo = (const float*)d_in[8];
    float* out = (float*)d_out;

    cudaFuncSetAttribute(attn_tc, cudaFuncAttributeMaxDynamicSharedMemorySize,
                         ATTN_SMEM_BYTES);

    proj3_tc<<<dim3(NN / 64, 6, BB), 256>>>(x, wt, bt, wp, bp, wg, bg);
    pool_kernel<<<(BB * MM * (CI / 4)) / 256, 256>>>();
    attn_tc<<<dim3(NN / 128, BB), 256, ATTN_SMEM_BYTES>>>();
    out_tc<<<dim3(NN / 64, CC / 64, BB), 256>>>(x, wo, bo, out);
}

// round 4
// speedup vs baseline: 3.0244x; 1.3859x over previous
#include <cuda_runtime.h>
#include <cuda_bf16.h>

// NonLocalAttention: B=8, C=256, Ci=128, H=W=64, N=4096, M=1024
#define BB 8
#define CC 256
#define CI 128
#define WW 64
#define NN 4096
#define MM 1024

__device__ float g_theta[(size_t)BB * NN * CI];
__device__ float g_phif [(size_t)BB * NN * CI];
__device__ float g_gf   [(size_t)BB * NN * CI];
__device__ float g_phip [(size_t)BB * MM * CI];
__device__ float g_gp   [(size_t)BB * MM * CI];
__device__ float g_y    [(size_t)BB * NN * CI];

// ---------------------------------------------------------------------------
// helpers
// ---------------------------------------------------------------------------
__device__ __forceinline__ unsigned cvt_tf32(float x) {
    unsigned u;
    asm("cvt.rna.tf32.f32 %0, %1;" : "=r"(u) : "f"(x));
    return u;
}
__device__ __forceinline__ void split4_tf32(float4 v, float4& h) {
    h.x = __uint_as_float(cvt_tf32(v.x));
    h.y = __uint_as_float(cvt_tf32(v.y));
    h.z = __uint_as_float(cvt_tf32(v.z));
    h.w = __uint_as_float(cvt_tf32(v.w));
}
// bf16 hi/lo split of two floats (k-pair), packed into bf16x2 words
__device__ __forceinline__ void pack2(unsigned& H, unsigned& L, float x0, float x1) {
    float h0 = __bfloat162float(__float2bfloat16_rn(x0));
    float h1 = __bfloat162float(__float2bfloat16_rn(x1));
    __nv_bfloat162 hh = __floats2bfloat162_rn(h0, h1);
    __nv_bfloat162 ll = __floats2bfloat162_rn(x0 - h0, x1 - h1);
    H = *(unsigned*)&hh;
    L = *(unsigned*)&ll;
}
__device__ __forceinline__ void mma16(float* c, unsigned a0, unsigned a1,
                                      unsigned a2, unsigned a3,
                                      unsigned b0, unsigned b1) {
    asm volatile(
        "mma.sync.aligned.m16n8k16.row.col.f32.bf16.bf16.f32 "
        "{%0,%1,%2,%3},{%4,%5,%6,%7},{%8,%9},{%0,%1,%2,%3};\n"
        : "+f"(c[0]), "+f"(c[1]), "+f"(c[2]), "+f"(c[3])
        : "r"(a0), "r"(a1), "r"(a2), "r"(a3), "r"(b0), "r"(b1));
}
__device__ __forceinline__ void mma8_tf32(float* c, unsigned a0, unsigned a1,
                                          unsigned a2, unsigned a3,
                                          unsigned b0, unsigned b1) {
    asm volatile(
        "mma.sync.aligned.m16n8k8.row.col.f32.tf32.tf32.f32 "
        "{%0,%1,%2,%3},{%4,%5,%6,%7},{%8,%9},{%0,%1,%2,%3};\n"
        : "+f"(c[0]), "+f"(c[1]), "+f"(c[2]), "+f"(c[3])
        : "r"(a0), "r"(a1), "r"(a2), "r"(a3), "r"(b0), "r"(b1));
}
#define FB(p) __float_as_uint(p)

// ---------------------------------------------------------------------------
// Kernel 1: 3-way 1x1 conv, bf16x3.  out[n][j] = sum_c x[c][n] w[j][c] + b[j]
// grid (N/64, 6, B); yy/2 selects proj, yy&1 selects 64-wide ci half.
// Block 64n x 64j, warp 16n x 32j, K chunks of 32 (2 k16 steps).
// Smem word-pitch 20 (=4 mod 8 -> conflict-free fragment LDS).
// ---------------------------------------------------------------------------
__global__ __launch_bounds__(256) void proj3_tc(
    const float* __restrict__ x,
    const float* __restrict__ w_t, const float* __restrict__ b_t,
    const float* __restrict__ w_p, const float* __restrict__ b_p,
    const float* __restrict__ w_g, const float* __restrict__ b_g)
{
    __shared__ unsigned Xh[64 * 20], Xl[64 * 20];   // x  [n][k-pair]
    __shared__ unsigned Wh[64 * 20], Wl[64 * 20];   // w  [j][k-pair]

    const int b  = blockIdx.z;
    const int n0 = blockIdx.x * 64;
    const int yy = blockIdx.y;

    const float* w;  const float* bias;  float* dst;
    if (yy < 2)      { w = w_t; bias = b_t; dst = g_theta; }
    else if (yy < 4) { w = w_p; bias = b_p; dst = g_phif; }
    else             { w = w_g; bias = b_g; dst = g_gf;  }
    const int cib = (yy & 1) * 64;

    const int tid  = threadIdx.x;
    const int lane = tid & 31, warp = tid >> 5;
    const int gid  = lane >> 2, t4 = lane & 3;
    const int mw   = (warp >> 1) * 16, nw = (warp & 1) * 32;

    float acc[4][4] = {};
    const float* xb = x + (size_t)b * CC * NN;

    const int xn  = tid & 63;        // n for x-transpose staging
    const int kp0 = tid >> 6;        // k-pair base

    for (int c0 = 0; c0 < CC; c0 += 32) {
        __syncthreads();
        // stage x transposed: [n][k-pair], scalar coalesced loads
        #pragma unroll
        for (int i = 0; i < 4; i++) {
            int kp = kp0 + i * 4;
            float v0 = xb[(size_t)(c0 + 2 * kp) * NN + n0 + xn];
            float v1 = xb[(size_t)(c0 + 2 * kp + 1) * NN + n0 + xn];
            unsigned H, L; pack2(H, L, v0, v1);
            Xh[xn * 20 + kp] = H;
            Xl[xn * 20 + kp] = L;
        }
        // stage w: k-contiguous float4 -> 2 packed words
        #pragma unroll
        for (int it = 0; it < 2; it++) {
            int j = tid + it * 256;
            int r = j >> 3, kq = j & 7;
            float4 v = *(const float4*)&w[(size_t)(cib + r) * CC + c0 + kq * 4];
            unsigned h0, l0, h1, l1;
            pack2(h0, l0, v.x, v.y);
            pack2(h1, l1, v.z, v.w);
            *(uint2*)&Wh[r * 20 + kq * 2] = make_uint2(h0, h1);
            *(uint2*)&Wl[r * 20 + kq * 2] = make_uint2(l0, l1);
        }
        __syncthreads();

        #pragma unroll
        for (int st = 0; st < 2; st++) {
            int kw = st * 8 + t4;
            int r0 = (mw + gid) * 20 + kw;
            int r1 = (mw + gid + 8) * 20 + kw;
            unsigned ah0 = Xh[r0], ah1 = Xh[r1], ah2 = Xh[r0 + 4], ah3 = Xh[r1 + 4];
            unsigned al0 = Xl[r0], al1 = Xl[r1], al2 = Xl[r0 + 4], al3 = Xl[r1 + 4];
            #pragma unroll
            for (int nt = 0; nt < 4; nt++) {
                int cb = (nw + nt * 8 + gid) * 20 + kw;
                unsigned bh0 = Wh[cb], bh1 = Wh[cb + 4];
                unsigned bl0 = Wl[cb], bl1 = Wl[cb + 4];
                mma16(acc[nt], ah0, ah1, ah2, ah3, bh0, bh1);
                mma16(acc[nt], ah0, ah1, ah2, ah3, bl0, bl1);
                mma16(acc[nt], al0, al1, al2, al3, bh0, bh1);
            }
        }
    }

    const size_t base = (size_t)b * NN + n0;
    #pragma unroll
    for (int nt = 0; nt < 4; nt++) {
        int col = cib + nw + nt * 8 + 2 * t4;
        float bb0 = bias[col], bb1 = bias[col + 1];
        int r0 = mw + gid;
        float2 v0 = {acc[nt][0] + bb0, acc[nt][1] + bb1};
        float2 v1 = {acc[nt][2] + bb0, acc[nt][3] + bb1};
        *(float2*)&dst[(base + r0) * CI + col]     = v0;
        *(float2*)&dst[(base + r0 + 8) * CI + col] = v1;
    }
}

// ---------------------------------------------------------------------------
// Kernel 2: 2x2 maxpool [B][N][Ci] -> [B][M][Ci]
// ---------------------------------------------------------------------------
__global__ __launch_bounds__(256) void pool_kernel()
{
    int idx = blockIdx.x * 256 + threadIdx.x;
    int c4 = (idx & 31) * 4;
    int m  = (idx >> 5) & (MM - 1);
    int b  = idx >> 15;
    int hp = m >> 5, wp = m & 31;
    int n00 = (hp * 2) * WW + wp * 2;
    size_t base = ((size_t)b * NN + n00) * CI + c4;
    size_t dst  = ((size_t)b * MM + m) * CI + c4;

    float4 a0 = *(const float4*)&g_phif[base];
    float4 a1 = *(const float4*)&g_phif[base + CI];
    float4 a2 = *(const float4*)&g_phif[base + (size_t)WW * CI];
    float4 a3 = *(const float4*)&g_phif[base + (size_t)WW * CI + CI];
    float4 r;
    r.x = fmaxf(fmaxf(a0.x, a1.x), fmaxf(a2.x, a3.x));
    r.y = fmaxf(fmaxf(a0.y, a1.y), fmaxf(a2.y, a3.y));
    r.z = fmaxf(fmaxf(a0.z, a1.z), fmaxf(a2.z, a3.z));
    r.w = fmaxf(fmaxf(a0.w, a1.w), fmaxf(a2.w, a3.w));
    *(float4*)&g_phip[dst] = r;

    a0 = *(const float4*)&g_gf[base];
    a1 = *(const float4*)&g_gf[base + CI];
    a2 = *(const float4*)&g_gf[base + (size_t)WW * CI];
    a3 = *(const float4*)&g_gf[base + (size_t)WW * CI + CI];
    r.x = fmaxf(fmaxf(a0.x, a1.x), fmaxf(a2.x, a3.x));
    r.y = fmaxf(fmaxf(a0.y, a1.y), fmaxf(a2.y, a3.y));
    r.z = fmaxf(fmaxf(a0.z, a1.z), fmaxf(a2.z, a3.z));
    r.w = fmaxf(fmaxf(a0.w, a1.w), fmaxf(a2.w, a3.w));
    *(float4*)&g_gp[dst] = r;
}

// ---------------------------------------------------------------------------
// Kernel 3: flash attention. QK^T = bf16x3 m16n8k16; PV = tf32 single pass.
// Block 128 q, 8 warps x 16 q, m tiles of 64.
// Q/K pre-split to bf16 hi/lo in smem (word pitch 68 = 4 mod 8).
// ---------------------------------------------------------------------------
#define ATTN_WORDS (2*128*68 + 2*64*68 + 64*136 + 128*68)
#define ATTN_SMEM_BYTES (ATTN_WORDS * 4)

__global__ __launch_bounds__(256, 1) void attn_tc()
{
    extern __shared__ unsigned smu[];
    unsigned* QhW = smu;                      // [q=128][kw=64] pitch 68
    unsigned* QlW = QhW + 128 * 68;
    unsigned* KhW = QlW + 128 * 68;           // [m=64][kw=64] pitch 68
    unsigned* KlW = KhW + 64 * 68;
    float*    Vh  = (float*)(KlW + 64 * 68);  // [m=64][ci=128] pitch 136 (tf32 hi)
    float*    Ps  = Vh + 64 * 136;            // [q=128][m=64] pitch 68

    const int b  = blockIdx.y;
    const int n0 = blockIdx.x * 128;
    const int tid  = threadIdx.x;
    const int lane = tid & 31, warp = tid >> 5;
    const int gid  = lane >> 2, t4 = lane & 3;
    const int qw   = warp * 16;

    // stage Q (hi/lo bf16, packed k-pairs)
    const float* Qg = g_theta + ((size_t)b * NN + n0) * CI;
    #pragma unroll
    for (int it = 0; it < 16; it++) {
        int j = tid + it * 256;
        int q = j >> 5, kq = j & 31;
        float4 v = *(const float4*)&Qg[(size_t)q * CI + kq * 4];
        unsigned h0, l0, h1, l1;
        pack2(h0, l0, v.x, v.y);
        pack2(h1, l1, v.z, v.w);
        *(uint2*)&QhW[q * 68 + kq * 2] = make_uint2(h0, h1);
        *(uint2*)&QlW[q * 68 + kq * 2] = make_uint2(l0, l1);
    }

    float o[16][4];
    #pragma unroll
    for (int i = 0; i < 16; i++)
        #pragma unroll
        for (int jj = 0; jj < 4; jj++) o[i][jj] = 0.f;
    float m_lo = -1e30f, m_hi = -1e30f, l_lo = 0.f, l_hi = 0.f;

    for (int m0 = 0; m0 < MM; m0 += 64) {
        __syncthreads();
        const float* Kg = g_phip + ((size_t)b * MM + m0) * CI;
        const float* Vg = g_gp   + ((size_t)b * MM + m0) * CI;
        #pragma unroll
        for (int it = 0; it < 8; it++) {
            int j = tid + it * 256;
            int m = j >> 5, kq = j & 31;
            float4 v = *(const float4*)&Kg[(size_t)m * CI + kq * 4];
            unsigned h0, l0, h1, l1;
            pack2(h0, l0, v.x, v.y);
            pack2(h1, l1, v.z, v.w);
            *(uint2*)&KhW[m * 68 + kq * 2] = make_uint2(h0, h1);
            *(uint2*)&KlW[m * 68 + kq * 2] = make_uint2(l0, l1);
            float4 vv = *(const float4*)&Vg[(size_t)m * CI + kq * 4];
            float4 vh; split4_tf32(vv, vh);
            *(float4*)&Vh[m * 136 + kq * 4] = vh;
        }
        __syncthreads();

        // S = Q K^T : bf16x3, 8 k16 steps
        float s[8][4];
        #pragma unroll
        for (int nt = 0; nt < 8; nt++)
            #pragma unroll
            for (int jj = 0; jj < 4; jj++) s[nt][jj] = 0.f;

        #pragma unroll
        for (int ks = 0; ks < 8; ks++) {
            int kw = ks * 8 + t4;
            int r0 = (qw + gid) * 68 + kw;
            int r1 = (qw + gid + 8) * 68 + kw;
            unsigned ah0 = QhW[r0], ah1 = QhW[r1], ah2 = QhW[r0 + 4], ah3 = QhW[r1 + 4];
            unsigned al0 = QlW[r0], al1 = QlW[r1], al2 = QlW[r0 + 4], al3 = QlW[r1 + 4];
            #pragma unroll
            for (int nt = 0; nt < 8; nt++) {
                int cb = (nt * 8 + gid) * 68 + kw;
                unsigned bh0 = KhW[cb], bh1 = KhW[cb + 4];
                unsigned bl0 = KlW[cb], bl1 = KlW[cb + 4];
                mma16(s[nt], ah0, ah1, ah2, ah3, bh0, bh1);
                mma16(s[nt], ah0, ah1, ah2, ah3, bl0, bl1);
                mma16(s[nt], al0, al1, al2, al3, bh0, bh1);
            }
        }

        // online softmax (rows qw+gid, qw+gid+8; cols spread over quad lanes)
        float mx0 = -1e30f, mx1 = -1e30f;
        #pragma unroll
        for (int nt = 0; nt < 8; nt++) {
            mx0 = fmaxf(mx0, fmaxf(s[nt][0], s[nt][1]));
            mx1 = fmaxf(mx1, fmaxf(s[nt][2], s[nt][3]));
        }
        mx0 = fmaxf(mx0, __shfl_xor_sync(0xffffffffu, mx0, 1));
        mx0 = fmaxf(mx0, __shfl_xor_sync(0xffffffffu, mx0, 2));
        mx1 = fmaxf(mx1, __shfl_xor_sync(0xffffffffu, mx1, 1));
        mx1 = fmaxf(mx1, __shfl_xor_sync(0xffffffffu, mx1, 2));
        float mn0 = fmaxf(m_lo, mx0), mn1 = fmaxf(m_hi, mx1);
        float al0 = __expf(m_lo - mn0), al1 = __expf(m_hi - mn1);
        float s0 = 0.f, s1 = 0.f;
        #pragma unroll
        for (int nt = 0; nt < 8; nt++) {
            float p0 = __expf(s[nt][0] - mn0);
            float p1 = __expf(s[nt][1] - mn0);
            float p2 = __expf(s[nt][2] - mn1);
            float p3 = __expf(s[nt][3] - mn1);
            s0 += p0 + p1; s1 += p2 + p3;
            float2 w0 = {p0, p1}, w1 = {p2, p3};
            *(float2*)&Ps[(qw + gid) * 68 + nt * 8 + 2 * t4]     = w0;
            *(float2*)&Ps[(qw + gid + 8) * 68 + nt * 8 + 2 * t4] = w1;
        }
        s0 += __shfl_xor_sync(0xffffffffu, s0, 1);
        s0 += __shfl_xor_sync(0xffffffffu, s0, 2);
        s1 += __shfl_xor_sync(0xffffffffu, s1, 1);
        s1 += __shfl_xor_sync(0xffffffffu, s1, 2);
        l_lo = l_lo * al0 + s0; m_lo = mn0;
        l_hi = l_hi * al1 + s1; m_hi = mn1;
        #pragma unroll
        for (int nt = 0; nt < 16; nt++) {
            o[nt][0] *= al0; o[nt][1] *= al0;
            o[nt][2] *= al1; o[nt][3] *= al1;
        }
        __syncwarp();

        // O += P V  (tf32 single pass)
        #pragma unroll
        for (int ks = 0; ks < 8; ks++) {
            int ko = ks * 8 + t4;
            unsigned ph0 = cvt_tf32(Ps[(qw + gid) * 68 + ko]);
            unsigned ph1 = cvt_tf32(Ps[(qw + gid + 8) * 68 + ko]);
            unsigned ph2 = cvt_tf32(Ps[(qw + gid) * 68 + ko + 4]);
            unsigned ph3 = cvt_tf32(Ps[(qw + gid + 8) * 68 + ko + 4]);
            #pragma unroll
            for (int nt = 0; nt < 16; nt++) {
                int cc = nt * 8 + gid;
                unsigned b0 = FB(Vh[ko * 136 + cc]);
                unsigned b1 = FB(Vh[(ko + 4) * 136 + cc]);
                mma8_tf32(o[nt], ph0, ph1, ph2, ph3, b0, b1);
            }
        }
    }

    float i0 = 1.f / l_lo, i1 = 1.f / l_hi;
    float* yb = g_y + ((size_t)b * NN + n0) * CI;
    #pragma unroll
    for (int nt = 0; nt < 16; nt++) {
        int cc = nt * 8 + 2 * t4;
        float2 w0 = {o[nt][0] * i0, o[nt][1] * i0};
        float2 w1 = {o[nt][2] * i1, o[nt][3] * i1};
        *(float2*)&yb[(size_t)(qw + gid) * CI + cc]     = w0;
        *(float2*)&yb[(size_t)(qw + gid + 8) * CI + cc] = w1;
    }
}

// ---------------------------------------------------------------------------
// Kernel 4: out conv + bias + residual, bf16x3.
// out[c][n] = x + bo[c] + sum_ci w[c][ci] y[n][ci]
// ---------------------------------------------------------------------------
__global__ __launch_bounds__(256) void out_tc(
    const float* __restrict__ x,
    const float* __restrict__ wo, const float* __restrict__ bo,
    float* __restrict__ out)
{
    __shared__ unsigned Ah[64 * 20], Al[64 * 20];   // wo [c][k-pair]
    __shared__ unsigned Bh[64 * 20], Bl[64 * 20];   // y  [n][k-pair]

    const int b  = blockIdx.z;
    const int c0 = blockIdx.y * 64;
    const int n0 = blockIdx.x * 64;
    const int tid  = threadIdx.x;
    const int lane = tid & 31, warp = tid >> 5;
    const int gid  = lane >> 2, t4 = lane & 3;
    const int mw   = (warp >> 1) * 16, nw = (warp & 1) * 32;

    const float* yb = g_y + ((size_t)b * NN + n0) * CI;
    float acc[4][4] = {};

    for (int k0 = 0; k0 < CI; k0 += 32) {
        __syncthreads();
        #pragma unroll
        for (int it = 0; it < 2; it++) {
            int j = tid + it * 256;
            int r = j >> 3, kq = j & 7;
            float4 a = *(const float4*)&wo[(size_t)(c0 + r) * CI + k0 + kq * 4];
            unsigned h0, l0, h1, l1;
            pack2(h0, l0, a.x, a.y);
            pack2(h1, l1, a.z, a.w);
            *(uint2*)&Ah[r * 20 + kq * 2] = make_uint2(h0, h1);
            *(uint2*)&Al[r * 20 + kq * 2] = make_uint2(l0, l1);
            float4 yv = *(const float4*)&yb[(size_t)r * CI + k0 + kq * 4];
            pack2(h0, l0, yv.x, yv.y);
            pack2(h1, l1, yv.z, yv.w);
            *(uint2*)&Bh[r * 20 + kq * 2] = make_uint2(h0, h1);
            *(uint2*)&Bl[r * 20 + kq * 2] = make_uint2(l0, l1);
        }
        __syncthreads();

        #pragma unroll
        for (int st = 0; st < 2; st++) {
            int kw = st * 8 + t4;
            int r0 = (mw + gid) * 20 + kw;
            int r1 = (mw + gid + 8) * 20 + kw;
            unsigned ah0 = Ah[r0], ah1 = Ah[r1], ah2 = Ah[r0 + 4], ah3 = Ah[r1 + 4];
            unsigned al0 = Al[r0], al1 = Al[r1], al2 = Al[r0 + 4], al3 = Al[r1 + 4];
            #pragma unroll
            for (int nt = 0; nt < 4; nt++) {
                int cb = (nw + nt * 8 + gid) * 20 + kw;
                unsigned bh0 = Bh[cb], bh1 = Bh[cb + 4];
                unsigned bl0 = Bl[cb], bl1 = Bl[cb + 4];
                mma16(acc[nt], ah0, ah1, ah2, ah3, bh0, bh1);
                mma16(acc[nt], ah0, ah1, ah2, ah3, bl0, bl1);
                mma16(acc[nt], al0, al1, al2, al3, bh0, bh1);
            }
        }
    }

    #pragma unroll
    for (int nt = 0; nt < 4; nt++) {
        int c = c0 + mw + gid;
        int n = n0 + nw + nt * 8 + 2 * t4;
        float bias0 = bo[c], bias1 = bo[c + 8];
        size_t off0 = ((size_t)b * CC + c) * NN + n;
        size_t off1 = ((size_t)b * CC + c + 8) * NN + n;
        float2 x0 = *(const float2*)&x[off0];
        float2 x1 = *(const float2*)&x[off1];
        float2 r0 = {acc[nt][0] + x0.x + bias0, acc[nt][1] + x0.y + bias0};
        float2 r1 = {acc[nt][2] + x1.x + bias1, acc[nt][3] + x1.y + bias1};
        *(float2*)&out[off0] = r0;
        *(float2*)&out[off1] = r1;
    }
}

// ---------------------------------------------------------------------------
extern "C" void kernel_launch(void* const* d_in, const int* in_sizes, int n_in,
                              void* d_out, int out_size)
{
    const float* x  = (const float*)d_in[0];
    const float* wt = (const float*)d_in[1];
    const float* bt = (const float*)d_in[2];
    const float* wp = (const float*)d_in[3];
    const float* bp = (const float*)d_in[4];
    const float* wg = (const float*)d_in[5];
    const float* bg = (const float*)d_in[6];
    const float* wo = (const float*)d_in[7];
    const float* bo = (const float*)d_in[8];
    float* out = (float*)d_out;

    cudaFuncSetAttribute(attn_tc, cudaFuncAttributeMaxDynamicSharedMemorySize,
                         ATTN_SMEM_BYTES);

    proj3_tc<<<dim3(NN / 64, 6, BB), 256>>>(x, wt, bt, wp, bp, wg, bg);
    pool_kernel<<<(BB * MM * (CI / 4)) / 256, 256>>>();
    attn_tc<<<dim3(NN / 128, BB), 256, ATTN_SMEM_BYTES>>>();
    out_tc<<<dim3(NN / 64, CC / 64, BB), 256>>>(x, wo, bo, out);
}